// round 9
// baseline (speedup 1.0000x reference)
#include <cuda_runtime.h>

// HSTU jagged causal attention, fp32, packed-f32x2 SIMT kernel.
// out[i,h,:] = sum_{j<=i, same seq} silu(q_i·k_j / sqrt(D)) / denom * v_j

#define H      8
#define Dh     128
#define DV     128
#define HD     (H * Dh)
#define BM     64
#define BN     32
#define NTHR   256

// shared memory layout (float offsets)
#define QT_OFF 0           // QT[d][i]      : [128][68]  (Q transposed, d-major)
#define QT_LD  68
#define KT_OFF 8704        // KT2[d][2j+e]  : [128][68]  (K transposed, each k duplicated)
#define KT_LD  68
#define SS_OFF 17408       // SS2[i][2j+e]  : [64][68]   (attn weights, duplicated)
#define SS_LD  68
#define VS_OFF 21760       // VS[j][c]      : [32][132]
#define VS_LD  132
#define SMEM_FLOATS 25984
#define SMEM_BYTES  (SMEM_FLOATS * 4)

typedef unsigned long long u64;

// packed fp32 FMA: d = a*b + d (two lanes per instruction, sm_100+)
__device__ __forceinline__ void ffma2(u64 &d, u64 a, u64 b) {
    asm("fma.rn.f32x2 %0, %1, %2, %0;" : "+l"(d) : "l"(a), "l"(b));
}
__device__ __forceinline__ float2 u2f(u64 v) {
    float2 f;
    asm("mov.b64 {%0, %1}, %2;" : "=f"(f.x), "=f"(f.y) : "l"(v));
    return f;
}

__global__ __launch_bounds__(NTHR, 2)
void hstu_attn_kernel(const float* __restrict__ tq,
                      const float* __restrict__ tk,
                      const float* __restrict__ tv,
                      const int*   __restrict__ offsets,
                      const int*   __restrict__ p_max_seqlen,
                      const int*   __restrict__ p_scaling,
                      float*       __restrict__ out)
{
    extern __shared__ float sm[];

    const int b  = blockIdx.z;
    const int h  = blockIdx.y;
    const int qt = gridDim.x - 1 - blockIdx.x;   // big tiles first (load balance)

    const int seq_start = offsets[b];
    const int L         = offsets[b + 1] - seq_start;
    const int i0        = qt * BM;
    if (i0 >= L) return;
    const int rows_valid = min(BM, L - i0);

    const int tid = threadIdx.x;

    const int   ms   = p_max_seqlen[0];
    const int   ssl  = p_scaling[0];
    const float invd = 1.0f / (float)(ssl > 0 ? ssl : ms);
    const float alpha = 0.08838834764831845f;    // 1/sqrt(128)

    // ---------------- load Q tile, transposed into QT[d][i] ----------------
    {
        const int il = tid & 63;          // local row
        const int dp = tid >> 6;          // 0..3 -> d base dp*32
        const float* qp = tq + (size_t)(seq_start + i0 + il) * HD + h * Dh + dp * 32;
        #pragma unroll
        for (int u = 0; u < 8; u++) {
            float4 v = make_float4(0.f, 0.f, 0.f, 0.f);
            if (il < rows_valid) v = *(const float4*)(qp + u * 4);
            const int d0 = dp * 32 + u * 4;
            sm[QT_OFF + (d0 + 0) * QT_LD + il] = v.x;
            sm[QT_OFF + (d0 + 1) * QT_LD + il] = v.y;
            sm[QT_OFF + (d0 + 2) * QT_LD + il] = v.z;
            sm[QT_OFF + (d0 + 3) * QT_LD + il] = v.w;
        }
    }

    // persistent O accumulators: 4 rows x 4 col-pairs (8 cols) per thread
    u64 acc[4][4];
    #pragma unroll
    for (int r = 0; r < 4; r++)
        #pragma unroll
        for (int p = 0; p < 4; p++) acc[r][p] = 0ull;

    const int jend = min(i0 + BM, L);
    const int nkt  = (jend + BN - 1) / BN;

    // stage A mapping: 16x16 grid, thread = 4 rows x 2 cols of S
    const int tyA = tid >> 4;     // rows tyA*4 .. +3
    const int txA = tid & 15;     // cols txA*2, txA*2+1
    // stage B mapping: 16x16 grid, thread = 4 rows x (cols txB*4..+3 and txB*4+64..+67)
    const int tyB = tid >> 4;
    const int txB = tid & 15;
    // loader mapping
    const int jl = tid & 31;
    const int dl = tid >> 5;      // 0..7 -> d base dl*16

    for (int kt = 0; kt < nkt; kt++) {
        const int j0 = kt * BN;
        __syncthreads();   // previous stage B done before overwriting KT2/VS (and Q visible)

        // ---- load K (transposed + duplicated) and V (row-major) ----
        {
            const bool ok = (j0 + jl) < L;
            const float* kp = tk + (size_t)(seq_start + j0 + jl) * HD + h * Dh + dl * 16;
            const float* vp = tv + (size_t)(seq_start + j0 + jl) * HD + h * DV + dl * 16;
            #pragma unroll
            for (int u = 0; u < 4; u++) {
                float4 kv = make_float4(0.f, 0.f, 0.f, 0.f);
                float4 vv = make_float4(0.f, 0.f, 0.f, 0.f);
                if (ok) { kv = *(const float4*)(kp + u * 4); vv = *(const float4*)(vp + u * 4); }
                const int d0 = dl * 16 + u * 4;
                *(float2*)&sm[KT_OFF + (d0 + 0) * KT_LD + 2 * jl] = make_float2(kv.x, kv.x);
                *(float2*)&sm[KT_OFF + (d0 + 1) * KT_LD + 2 * jl] = make_float2(kv.y, kv.y);
                *(float2*)&sm[KT_OFF + (d0 + 2) * KT_LD + 2 * jl] = make_float2(kv.z, kv.z);
                *(float2*)&sm[KT_OFF + (d0 + 3) * KT_LD + 2 * jl] = make_float2(kv.w, kv.w);
                *(float4*)&sm[VS_OFF + jl * VS_LD + d0] = vv;
            }
        }
        __syncthreads();

        // ---- stage A: S = Q . K^T (packed over row pairs), silu, write dup ----
        {
            u64 s[2][2] = {{0ull, 0ull}, {0ull, 0ull}};
            #pragma unroll 4
            for (int d = 0; d < Dh; d++) {
                // qq.x = (Q[ty*4][d], Q[ty*4+1][d]); qq.y = rows +2,+3
                ulonglong2 qq = *(const ulonglong2*)&sm[QT_OFF + d * QT_LD + tyA * 4];
                // kk.x = (k_{2tx}, k_{2tx}); kk.y = (k_{2tx+1}, k_{2tx+1})
                ulonglong2 kk = *(const ulonglong2*)&sm[KT_OFF + d * KT_LD + txA * 4];
                ffma2(s[0][0], qq.x, kk.x);
                ffma2(s[0][1], qq.x, kk.y);
                ffma2(s[1][0], qq.y, kk.x);
                ffma2(s[1][1], qq.y, kk.y);
            }
            #pragma unroll
            for (int rp = 0; rp < 2; rp++) {
                #pragma unroll
                for (int c = 0; c < 2; c++) {
                    float2 sv = u2f(s[rp][c]);
                    const int r0 = tyA * 4 + rp * 2;
                    const int j  = txA * 2 + c;
                    float x0 = sv.x * alpha;
                    float a0 = __fdividef(x0, 1.0f + __expf(-x0)) * invd;
                    if (j0 + j > i0 + r0) a0 = 0.0f;           // causal mask
                    float x1 = sv.y * alpha;
                    float a1 = __fdividef(x1, 1.0f + __expf(-x1)) * invd;
                    if (j0 + j > i0 + r0 + 1) a1 = 0.0f;
                    *(float2*)&sm[SS_OFF + (r0    ) * SS_LD + 2 * j] = make_float2(a0, a0);
                    *(float2*)&sm[SS_OFF + (r0 + 1) * SS_LD + 2 * j] = make_float2(a1, a1);
                }
            }
        }
        __syncthreads();

        // ---- stage B: O += S . V (splat-S x natural V pairs) ----
        {
            #pragma unroll 2
            for (int jj = 0; jj < BN; jj += 2) {
                ulonglong2 va = *(const ulonglong2*)&sm[VS_OFF + (jj    ) * VS_LD + txB * 4];
                ulonglong2 vb = *(const ulonglong2*)&sm[VS_OFF + (jj    ) * VS_LD + txB * 4 + 64];
                ulonglong2 wa = *(const ulonglong2*)&sm[VS_OFF + (jj + 1) * VS_LD + txB * 4];
                ulonglong2 wb = *(const ulonglong2*)&sm[VS_OFF + (jj + 1) * VS_LD + txB * 4 + 64];
                #pragma unroll
                for (int r = 0; r < 4; r++) {
                    // sp.x = (s_jj, s_jj); sp.y = (s_{jj+1}, s_{jj+1})
                    ulonglong2 sp = *(const ulonglong2*)&sm[SS_OFF + (tyB * 4 + r) * SS_LD + 2 * jj];
                    ffma2(acc[r][0], sp.x, va.x);
                    ffma2(acc[r][1], sp.x, va.y);
                    ffma2(acc[r][2], sp.x, vb.x);
                    ffma2(acc[r][3], sp.x, vb.y);
                    ffma2(acc[r][0], sp.y, wa.x);
                    ffma2(acc[r][1], sp.y, wa.y);
                    ffma2(acc[r][2], sp.y, wb.x);
                    ffma2(acc[r][3], sp.y, wb.y);
                }
            }
        }
    }

    // ---------------- epilogue: store O ----------------
    #pragma unroll
    for (int r = 0; r < 4; r++) {
        const int row = tyB * 4 + r;
        if (row < rows_valid) {
            float* op = out + (size_t)(seq_start + i0 + row) * (H * DV) + h * DV + txB * 4;
            float2 p0 = u2f(acc[r][0]);
            float2 p1 = u2f(acc[r][1]);
            float2 p2 = u2f(acc[r][2]);
            float2 p3 = u2f(acc[r][3]);
            *(float4*)(op)      = make_float4(p0.x, p0.y, p1.x, p1.y);
            *(float4*)(op + 64) = make_float4(p2.x, p2.y, p3.x, p3.y);
        }
    }
}

extern "C" void kernel_launch(void* const* d_in, const int* in_sizes, int n_in,
                              void* d_out, int out_size)
{
    const float* tq      = (const float*)d_in[0];
    const float* tk      = (const float*)d_in[1];
    const float* tv      = (const float*)d_in[2];
    const int*   offsets = (const int*)d_in[3];
    const int*   msp     = (const int*)d_in[4];
    const int*   ssp     = (const int*)d_in[5];
    float*       out     = (float*)d_out;

    const int B     = in_sizes[3] - 1;
    const int total = in_sizes[0] / HD;
    const int maxtiles = (total + BM - 1) / BM;   // upper bound on any sequence's tiles

    cudaFuncSetAttribute(hstu_attn_kernel,
                         cudaFuncAttributeMaxDynamicSharedMemorySize, SMEM_BYTES);

    dim3 grid(maxtiles, H, B);
    hstu_attn_kernel<<<grid, NTHR, SMEM_BYTES>>>(tq, tk, tv, offsets, msp, ssp, out);
}

// round 14
// speedup vs baseline: 2.0449x; 2.0449x over previous
#include <cuda_runtime.h>
#include <cuda_bf16.h>
#include <cstdint>

// HSTU jagged causal attention via mma.sync (HMMA) bf16 3-way split.
// S = Q.K^T -> silu -> O += S.V ; fp32 accumulation, S stays in registers.

#define H     8
#define Dh    128
#define HD    1024
#define BM    128
#define BN    64
#define NTHR  256
#define LDSd  136                       // padded smem row stride (bf16 elems)

#define QH_OFF 0
#define QL_OFF (BM * LDSd * 2)          // 34816
#define KH_OFF (2 * BM * LDSd * 2)      // 69632
#define KL_OFF (KH_OFF + BN * LDSd * 2) // 87040
#define VH_OFF (KL_OFF + BN * LDSd * 2) // 104448
#define VL_OFF (VH_OFF + BN * LDSd * 2) // 121856
#define SMEM_BYTES (VL_OFF + BN * LDSd * 2)  // 139264

__device__ __forceinline__ uint32_t smem_u32(const void* p) {
    uint32_t a;
    asm("{ .reg .u64 t; cvta.to.shared.u64 t, %1; cvt.u32.u64 %0, t; }" : "=r"(a) : "l"(p));
    return a;
}
__device__ __forceinline__ void ldm_x4(uint32_t* r, uint32_t a) {
    asm volatile("ldmatrix.sync.aligned.m8n8.x4.shared.b16 {%0,%1,%2,%3}, [%4];"
                 : "=r"(r[0]), "=r"(r[1]), "=r"(r[2]), "=r"(r[3]) : "r"(a));
}
__device__ __forceinline__ void ldm_x2(uint32_t* r, uint32_t a) {
    asm volatile("ldmatrix.sync.aligned.m8n8.x2.shared.b16 {%0,%1}, [%2];"
                 : "=r"(r[0]), "=r"(r[1]) : "r"(a));
}
__device__ __forceinline__ void ldm_x2t(uint32_t* r, uint32_t a) {
    asm volatile("ldmatrix.sync.aligned.m8n8.x2.trans.shared.b16 {%0,%1}, [%2];"
                 : "=r"(r[0]), "=r"(r[1]) : "r"(a));
}
__device__ __forceinline__ void mma16816(float* d, const uint32_t* a, const uint32_t* b) {
    asm volatile("mma.sync.aligned.m16n8k16.row.col.f32.bf16.bf16.f32 "
                 "{%0,%1,%2,%3}, {%4,%5,%6,%7}, {%8,%9}, {%0,%1,%2,%3};"
                 : "+f"(d[0]), "+f"(d[1]), "+f"(d[2]), "+f"(d[3])
                 : "r"(a[0]), "r"(a[1]), "r"(a[2]), "r"(a[3]), "r"(b[0]), "r"(b[1]));
}
__device__ __forceinline__ uint32_t pkbf(__nv_bfloat16 a, __nv_bfloat16 b) {
    return (uint32_t)__bfloat16_as_ushort(a) | ((uint32_t)__bfloat16_as_ushort(b) << 16);
}
// split two fp32 into packed hi / packed lo bf16x2
__device__ __forceinline__ void split2(float a, float b, uint32_t& hh, uint32_t& ll) {
    __nv_bfloat16 ha = __float2bfloat16(a), hb = __float2bfloat16(b);
    __nv_bfloat16 la = __float2bfloat16(a - __bfloat162float(ha));
    __nv_bfloat16 lb = __float2bfloat16(b - __bfloat162float(hb));
    hh = pkbf(ha, hb); ll = pkbf(la, lb);
}
__device__ __forceinline__ void split_store(float v, char* base_h, char* base_l, uint32_t eoff) {
    __nv_bfloat16 hi = __float2bfloat16(v);
    __nv_bfloat16 lo = __float2bfloat16(v - __bfloat162float(hi));
    *(__nv_bfloat16*)(base_h + 2 * eoff) = hi;
    *(__nv_bfloat16*)(base_l + 2 * eoff) = lo;
}

__global__ __launch_bounds__(NTHR, 1)
void hstu_hmma_kernel(const float* __restrict__ tq,
                      const float* __restrict__ tk,
                      const float* __restrict__ tv,
                      const int*   __restrict__ offsets,
                      const int*   __restrict__ p_ms,
                      const int*   __restrict__ p_ssl,
                      float*       __restrict__ out)
{
    extern __shared__ char smem[];
    const uint32_t sb = smem_u32(smem);

    const int b  = blockIdx.z;
    const int h  = blockIdx.y;
    const int qt = gridDim.x - 1 - blockIdx.x;     // big tiles first

    const int seq = offsets[b];
    const int L   = offsets[b + 1] - seq;
    const int i0  = qt * BM;
    if (i0 >= L) return;
    const int rows_valid = min(BM, L - i0);

    const int tid  = threadIdx.x;
    const int w    = tid >> 5;
    const int lane = tid & 31;

    const int   ssl  = p_ssl[0];
    const float invd = 1.0f / (float)(ssl > 0 ? ssl : p_ms[0]);
    const float alpha = 0.08838834764831845f;      // 1/sqrt(128)

    // ---- load Q once: fp32 -> hi/lo bf16 in padded rows ----
    for (int idx = tid; idx < BM * Dh; idx += NTHR) {
        const int row = idx >> 7, col = idx & 127;
        float v = (row < rows_valid) ? tq[(size_t)(seq + i0 + row) * HD + h * Dh + col] : 0.0f;
        split_store(v, smem + QH_OFF, smem + QL_OFF, (uint32_t)(row * LDSd + col));
    }

    // ---- O accumulators: warp = 16 rows x 128 dv ----
    float o[16][4];
    #pragma unroll
    for (int nn = 0; nn < 16; nn++)
        #pragma unroll
        for (int e = 0; e < 4; e++) o[nn][e] = 0.0f;

    // ldmatrix base addresses (per lane)
    const uint32_t aq_h = sb + QH_OFF + (uint32_t)(((w * 16) + (lane & 15)) * LDSd + ((lane >> 4) << 3)) * 2;
    const uint32_t aq_l = aq_h + (QL_OFF - QH_OFF);
    const uint32_t bk_h = sb + KH_OFF + (uint32_t)((lane & 7) * LDSd + (((lane >> 3) & 1) << 3)) * 2;
    const uint32_t bk_l = bk_h + (KL_OFF - KH_OFF);
    const uint32_t bv_h = sb + VH_OFF + (uint32_t)((lane & 15) * LDSd) * 2;
    const uint32_t bv_l = bv_h + (VL_OFF - VH_OFF);

    const int r_lo = lane >> 2;          // 0..7
    const int c_lo = (lane & 3) * 2;
    const int row0 = i0 + w * 16 + r_lo;

    const int jend = min(i0 + BM, L);
    const int nkt  = (jend + BN - 1) / BN;

    for (int kt = 0; kt < nkt; kt++) {
        const int j0 = kt * BN;

        // ---- load K and V (hi/lo split) ----
        for (int idx = tid; idx < BN * Dh; idx += NTHR) {
            const int kr = idx >> 7, col = idx & 127;
            const bool ok = (j0 + kr) < L;
            float kv = ok ? tk[(size_t)(seq + j0 + kr) * HD + h * Dh + col] : 0.0f;
            float vv = ok ? tv[(size_t)(seq + j0 + kr) * HD + h * Dh + col] : 0.0f;
            const uint32_t eoff = (uint32_t)(kr * LDSd + col);
            split_store(kv, smem + KH_OFF, smem + KL_OFF, eoff);
            split_store(vv, smem + VH_OFF, smem + VL_OFF, eoff);
        }
        __syncthreads();

        // warp-level causal skip: this warp's rows all < j0 -> contribution is 0
        if (j0 <= i0 + w * 16 + 15) {
            // ---- MMA1: S[16][64] = Qh.Kh^T + Qh.Kl^T + Ql.Kh^T ----
            float s[8][4];
            #pragma unroll
            for (int nb = 0; nb < 8; nb++)
                #pragma unroll
                for (int e = 0; e < 4; e++) s[nb][e] = 0.0f;

            #pragma unroll
            for (int k = 0; k < 8; k++) {
                uint32_t ah[4], al[4];
                ldm_x4(ah, aq_h + k * 32);
                ldm_x4(al, aq_l + k * 32);
                #pragma unroll
                for (int nb = 0; nb < 8; nb++) {
                    uint32_t bh[2], bl[2];
                    const uint32_t boff = (uint32_t)nb * (8 * LDSd * 2) + (uint32_t)k * 32;
                    ldm_x2(bh, bk_h + boff);
                    ldm_x2(bl, bk_l + boff);
                    mma16816(s[nb], ah, bh);
                    mma16816(s[nb], ah, bl);
                    mma16816(s[nb], al, bh);
                }
            }

            // ---- silu + scale + causal mask (in registers) ----
            #pragma unroll
            for (int nb = 0; nb < 8; nb++) {
                #pragma unroll
                for (int e = 0; e < 4; e++) {
                    const int row = row0 + ((e >> 1) << 3);
                    const int col = j0 + nb * 8 + c_lo + (e & 1);
                    float x = s[nb][e] * alpha;
                    float a = __fdividef(x, 1.0f + __expf(-x)) * invd;
                    s[nb][e] = (col <= row) ? a : 0.0f;
                }
            }

            // ---- MMA2: O += Sh.Vh + Sh.Vl + Sl.Vh (S frags from registers) ----
            #pragma unroll
            for (int kk = 0; kk < 4; kk++) {
                uint32_t ah[4], al[4];
                split2(s[2 * kk][0],     s[2 * kk][1],     ah[0], al[0]);
                split2(s[2 * kk][2],     s[2 * kk][3],     ah[1], al[1]);
                split2(s[2 * kk + 1][0], s[2 * kk + 1][1], ah[2], al[2]);
                split2(s[2 * kk + 1][2], s[2 * kk + 1][3], ah[3], al[3]);
                #pragma unroll
                for (int nn = 0; nn < 16; nn++) {
                    uint32_t bh[2], bl[2];
                    const uint32_t voff = (uint32_t)kk * (16 * LDSd * 2) + (uint32_t)nn * 16;
                    ldm_x2t(bh, bv_h + voff);
                    ldm_x2t(bl, bv_l + voff);
                    mma16816(o[nn], ah, bh);
                    mma16816(o[nn], ah, bl);
                    mma16816(o[nn], al, bh);
                }
            }
        }
        __syncthreads();
    }

    // ---- store O ----
    const int lr0 = w * 16 + r_lo;
    #pragma unroll
    for (int nn = 0; nn < 16; nn++) {
        const int c = nn * 8 + c_lo;
        if (lr0 < rows_valid) {
            float* op = out + (size_t)(seq + i0 + lr0) * HD + h * Dh + c;
            *(float2*)op = make_float2(o[nn][0], o[nn][1]);
        }
        if (lr0 + 8 < rows_valid) {
            float* op = out + (size_t)(seq + i0 + lr0 + 8) * HD + h * Dh + c;
            *(float2*)op = make_float2(o[nn][2], o[nn][3]);
        }
    }
}

extern "C" void kernel_launch(void* const* d_in, const int* in_sizes, int n_in,
                              void* d_out, int out_size)
{
    const float* tq      = (const float*)d_in[0];
    const float* tk      = (const float*)d_in[1];
    const float* tv      = (const float*)d_in[2];
    const int*   offsets = (const int*)d_in[3];
    const int*   msp     = (const int*)d_in[4];
    const int*   ssp     = (const int*)d_in[5];
    float*       out     = (float*)d_out;

    const int B        = in_sizes[3] - 1;
    const int total    = in_sizes[0] / HD;
    const int maxtiles = (total + BM - 1) / BM;

    cudaFuncSetAttribute(hstu_hmma_kernel,
                         cudaFuncAttributeMaxDynamicSharedMemorySize, SMEM_BYTES);

    dim3 grid(maxtiles, H, B);
    hstu_hmma_kernel<<<grid, NTHR, SMEM_BYTES>>>(tq, tk, tv, offsets, msp, ssp, out);
}